// round 11
// baseline (speedup 1.0000x reference)
#include <cuda_runtime.h>

#define Nn 50000
#define Ee 600000
#define Hh 128
#define Gg 64

#define SCAN_T 512
#define SCAN_B ((Nn + SCAN_T - 1) / SCAN_T)   // 98

// ---- static scratch ----
__device__ float g_h[Nn * Hh];
__device__ float g_P[Nn * Hh];      // gemm self-loop-init output
__device__ float g_Q[Nn * Hh];      // aggregated output
__device__ float g_dinv[Nn];
__device__ int   g_deg[Nn];         // edge-in count (no self loop)
__device__ int   g_rank[Ee];        // per-edge slot within its dst row
__device__ int   g_rowptr[Nn + 1];
__device__ int   g_bsum[SCAN_B];
__device__ int2  g_csr[Ee];
__device__ float g_pooled[Gg * Hh];

// ------------------------------------------------------------------
__global__ void init_kernel() {
    int i = blockIdx.x * blockDim.x + threadIdx.x;
    if (i < Nn) g_deg[i] = 0;
    if (i == 0) g_rowptr[Nn] = Ee;
}

// deg count; returned old value is this edge's unique rank in its row
__global__ void deg_kernel(const int* __restrict__ dst) {
    int e = blockIdx.x * blockDim.x + threadIdx.x;
    if (e < Ee) g_rank[e] = atomicAdd(&g_deg[dst[e]], 1);
}

// ---- block sums of deg (CSR counts) + dinv = rsqrt(deg+1) ----
__global__ void scanA_kernel() {
    __shared__ int ws[16];
    int tid = threadIdx.x;
    int i = blockIdx.x * SCAN_T + tid;
    int v = 0;
    if (i < Nn) {
        int d = g_deg[i];
        v = d;
        g_dinv[i] = rsqrtf((float)(d + 1));
    }
#pragma unroll
    for (int o = 16; o; o >>= 1) v += __shfl_down_sync(0xffffffffu, v, o);
    if ((tid & 31) == 0) ws[tid >> 5] = v;
    __syncthreads();
    if (tid < 32) {
        int t = (tid < 16) ? ws[tid] : 0;
#pragma unroll
        for (int o = 8; o; o >>= 1) t += __shfl_down_sync(0xffffffffu, t, o);
        if (tid == 0) g_bsum[blockIdx.x] = t;
    }
}

// ---- full exclusive scan: per-block prefix + fused block-offset reduce ----
__global__ void scanC_kernel() {
    __shared__ int wsum[16], woff[16];
    __shared__ int s_boff;
    int tid = threadIdx.x;
    int lane = tid & 31, wid = tid >> 5;
    int i = blockIdx.x * SCAN_T + tid;
    int v = (i < Nn) ? g_deg[i] : 0;
    int incl = v;
#pragma unroll
    for (int o = 1; o < 32; o <<= 1) {
        int u = __shfl_up_sync(0xffffffffu, incl, o);
        if (lane >= o) incl += u;
    }
    if (lane == 31) wsum[wid] = incl;
    __syncthreads();
    if (tid < 32) {
        int t = (tid < 16) ? wsum[tid] : 0;
        int inc = t;
#pragma unroll
        for (int o = 1; o < 16; o <<= 1) {
            int u = __shfl_up_sync(0xffffffffu, inc, o);
            if (lane >= o) inc += u;
        }
        if (tid < 16) woff[tid] = inc - t;
        int acc = 0;
        for (int t2 = lane; t2 < blockIdx.x; t2 += 32) acc += g_bsum[t2];
#pragma unroll
        for (int o = 16; o; o >>= 1) acc += __shfl_down_sync(0xffffffffu, acc, o);
        if (lane == 0) s_boff = acc;
    }
    __syncthreads();
    if (i < Nn) g_rowptr[i] = incl - v + woff[wid] + s_boff;
}

// atomic-free CSR fill using precomputed ranks
__global__ void fill_kernel(const int* __restrict__ src, const int* __restrict__ dst) {
    int e = blockIdx.x * blockDim.x + threadIdx.x;
    if (e >= Ee) return;
    int s = src[e], d = dst[e];
    int p = g_rowptr[d] + g_rank[e];
    g_csr[p] = make_int2(s, __float_as_int(g_dinv[s] * g_dinv[d]));
}

// ------------------------------------------------------------------
// GEMM: h = f(in) @ W  (f = relu(v+bprev) if apply_f)
// Packed f32x2 FMA with PRE-DUPLICATED input tile in smem:
// in_d[row][k] = (v, v) as float2 -> inner loop has zero packing MOVs,
// one LDS.64 broadcast per (row,k).
// Tile 64x128, 512 threads, 4x4 microtile (acc 4 rows x 2 f32x2 pairs).
// Epilogue: hout = h, accout = h * dinv^2 (self-loop).
// ------------------------------------------------------------------
__global__ void __launch_bounds__(512, 1)
gemm_kernel(const float* __restrict__ in, const float* __restrict__ W,
            const float* __restrict__ bprev, int apply_f,
            float* __restrict__ hout, float* __restrict__ accout) {
    extern __shared__ float sm[];
    float2* in_d = (float2*)sm;             // [64][128] duplicated, 64 KB
    float*  W_s  = sm + 64 * Hh * 2;        // [128][128], 64 KB
    int tid = threadIdx.x;
    int r0 = blockIdx.x * 64;

    // load W (128x128): 4096 float4 / 512 threads = 8 each
#pragma unroll
    for (int i = 0; i < 8; i++) {
        int fid = tid + i * 512;
        ((float4*)W_s)[fid] = ((const float4*)W)[fid];
    }
    // load input tile (64x128): 2048 float4 / 512 = 4 each; fused bias+relu;
    // store duplicated (v,v) pairs
#pragma unroll
    for (int i = 0; i < 4; i++) {
        int fid = tid + i * 512;
        int row = fid >> 5, c4 = fid & 31;
        float4 v = make_float4(0.f, 0.f, 0.f, 0.f);
        if (r0 + row < Nn) {
            v = ((const float4*)(in + (size_t)(r0 + row) * Hh))[c4];
            if (apply_f) {
                float4 b = ((const float4*)bprev)[c4];
                v.x = fmaxf(v.x + b.x, 0.f);
                v.y = fmaxf(v.y + b.y, 0.f);
                v.z = fmaxf(v.z + b.z, 0.f);
                v.w = fmaxf(v.w + b.w, 0.f);
            }
        }
        float2* p = in_d + row * Hh + c4 * 4;
        p[0] = make_float2(v.x, v.x);
        p[1] = make_float2(v.y, v.y);
        p[2] = make_float2(v.z, v.z);
        p[3] = make_float2(v.w, v.w);
    }
    __syncthreads();

    int tx = tid & 31;   // col quad: cols tx*4 .. tx*4+3
    int ty = tid >> 5;   // row quad: rows ty*4 .. ty*4+3 (warp-uniform)

    const unsigned long long* a_base =
        (const unsigned long long*)(in_d + ty * 4 * Hh);
    const float* w_base = W_s + tx * 4;

    unsigned long long acc[4][2];
#pragma unroll
    for (int r = 0; r < 4; r++) { acc[r][0] = 0ull; acc[r][1] = 0ull; }

#pragma unroll 8
    for (int k = 0; k < Hh; k++) {
        longlong2 bp = *(const longlong2*)(w_base + k * Hh);
        unsigned long long b0 = (unsigned long long)bp.x;
        unsigned long long b1 = (unsigned long long)bp.y;
#pragma unroll
        for (int r = 0; r < 4; r++) {
            unsigned long long a2 = a_base[r * Hh + k];   // LDS.64 broadcast
            asm("fma.rn.f32x2 %0, %1, %2, %0;" : "+l"(acc[r][0]) : "l"(a2), "l"(b0));
            asm("fma.rn.f32x2 %0, %1, %2, %0;" : "+l"(acc[r][1]) : "l"(a2), "l"(b1));
        }
    }

#pragma unroll
    for (int r = 0; r < 4; r++) {
        int row = r0 + ty * 4 + r;
        if (row < Nn) {
            float di = g_dinv[row];
            float d2 = di * di;
            float v[4];
            asm("mov.b64 {%0, %1}, %2;" : "=f"(v[0]), "=f"(v[1]) : "l"(acc[r][0]));
            asm("mov.b64 {%0, %1}, %2;" : "=f"(v[2]), "=f"(v[3]) : "l"(acc[r][1]));
            ((float4*)(hout + (size_t)row * Hh + tx * 4))[0] =
                make_float4(v[0], v[1], v[2], v[3]);
            ((float4*)(accout + (size_t)row * Hh + tx * 4))[0] =
                make_float4(v[0] * d2, v[1] * d2, v[2] * d2, v[3] * d2);
        }
    }
}

// ------------------------------------------------------------------
// Aggregation: warp per node, non-atomic, pipelined edge fetch. (R6-proven)
// ------------------------------------------------------------------
__global__ void agg_kernel(const float* __restrict__ h, const float* __restrict__ init,
                           float* __restrict__ out) {
    int warp = (blockIdx.x * blockDim.x + threadIdx.x) >> 5;
    int lane = threadIdx.x & 31;
    if (warp >= Nn) return;
    int beg = g_rowptr[warp], end = g_rowptr[warp + 1];
    float4 acc = ((const float4*)(init + (size_t)warp * Hh))[lane];
    int2 e = make_int2(0, 0);
    if (beg < end) e = g_csr[beg];
    for (int j = beg; j < end; j++) {
        int2 cur = e;
        if (j + 1 < end) e = g_csr[j + 1];
        float w = __int_as_float(cur.y);
        float4 v = ((const float4*)(h + (size_t)cur.x * Hh))[lane];
        acc.x = fmaf(w, v.x, acc.x);
        acc.y = fmaf(w, v.y, acc.y);
        acc.z = fmaf(w, v.z, acc.z);
        acc.w = fmaf(w, v.w, acc.w);
    }
    ((float4*)(out + (size_t)warp * Hh))[lane] = acc;
}

// ------------------------------------------------------------------
__device__ __forceinline__ int lower_bound_dev(const int* a, int n, int key) {
    int lo = 0, hi = n;
    while (lo < hi) {
        int mid = (lo + hi) >> 1;
        if (a[mid] < key) lo = mid + 1; else hi = mid;
    }
    return lo;
}

__global__ void pool_kernel(const int* __restrict__ batch, const float* __restrict__ acc,
                            const float* __restrict__ b3) {
    int g = blockIdx.x;
    int f = threadIdx.x;
    __shared__ int s_lo, s_hi;
    if (f == 0) s_lo = lower_bound_dev(batch, Nn, g);
    if (f == 1) s_hi = lower_bound_dev(batch, Nn, g + 1);
    __syncthreads();
    int lo = s_lo, hi = s_hi;
    float b = b3[f];
    float s0 = 0.f, s1 = 0.f, s2 = 0.f, s3 = 0.f;
    int n = lo;
    for (; n + 4 <= hi; n += 4) {
        s0 += fmaxf(acc[(size_t)(n + 0) * Hh + f] + b, 0.f);
        s1 += fmaxf(acc[(size_t)(n + 1) * Hh + f] + b, 0.f);
        s2 += fmaxf(acc[(size_t)(n + 2) * Hh + f] + b, 0.f);
        s3 += fmaxf(acc[(size_t)(n + 3) * Hh + f] + b, 0.f);
    }
    for (; n < hi; n++) s0 += fmaxf(acc[(size_t)n * Hh + f] + b, 0.f);
    float s = (s0 + s1) + (s2 + s3);
    g_pooled[g * Hh + f] = s / fmaxf((float)(hi - lo), 1.f);
}

__global__ void final_kernel(const float* __restrict__ Wl, const float* __restrict__ bl,
                             float* __restrict__ out) {
    int t = threadIdx.x;
    int g = t >> 1, c = t & 1;
    float s = 0.f;
#pragma unroll 8
    for (int k = 0; k < Hh; k++)
        s += g_pooled[g * Hh + k] * Wl[k * 2 + c];
    out[g * 2 + c] = s + bl[c];
}

// ------------------------------------------------------------------
extern "C" void kernel_launch(void* const* d_in, const int* in_sizes, int n_in,
                              void* d_out, int out_size) {
    const float* x     = (const float*)d_in[0];
    const int*   ei    = (const int*)d_in[1];
    const int*   batch = (const int*)d_in[2];
    const float* W1 = (const float*)d_in[3];
    const float* b1 = (const float*)d_in[4];
    const float* W2 = (const float*)d_in[5];
    const float* b2 = (const float*)d_in[6];
    const float* W3 = (const float*)d_in[7];
    const float* b3 = (const float*)d_in[8];
    const float* Wl = (const float*)d_in[9];
    const float* bl = (const float*)d_in[10];
    float* out = (float*)d_out;

    const int* src = ei;
    const int* dst = ei + Ee;

    float *hptr, *P, *Q;
    cudaGetSymbolAddress((void**)&hptr, g_h);
    cudaGetSymbolAddress((void**)&P, g_P);
    cudaGetSymbolAddress((void**)&Q, g_Q);

    const int SMEM = (64 * Hh * 2 + Hh * Hh) * sizeof(float);   // 128 KB
    cudaFuncSetAttribute(gemm_kernel, cudaFuncAttributeMaxDynamicSharedMemorySize, SMEM);

    int gemm_blocks = (Nn + 63) / 64;                // 782
    int agg_blocks  = (Nn * 32 + 255) / 256;

    // #1..#3: minimal prefix so gemm1 is launch #4 (ncu captures #4)
    init_kernel<<<(Nn + 255) / 256, 256>>>();
    deg_kernel<<<(Ee + 255) / 256, 256>>>(dst);      // also writes ranks
    scanA_kernel<<<SCAN_B, SCAN_T>>>();              // block sums + dinv

    // #4: layer-1 GEMM (needs only dinv)
    gemm_kernel<<<gemm_blocks, 512, SMEM>>>(x, W1, nullptr, 0, hptr, P);

    // finish CSR build, then aggregate
    scanC_kernel<<<SCAN_B, SCAN_T>>>();
    fill_kernel<<<(Ee + 255) / 256, 256>>>(src, dst);
    agg_kernel<<<agg_blocks, 256>>>(hptr, P, Q);

    // Layer 2
    gemm_kernel<<<gemm_blocks, 512, SMEM>>>(Q, W2, b1, 1, hptr, P);
    agg_kernel<<<agg_blocks, 256>>>(hptr, P, Q);
    // Layer 3
    gemm_kernel<<<gemm_blocks, 512, SMEM>>>(Q, W3, b2, 1, hptr, P);
    agg_kernel<<<agg_blocks, 256>>>(hptr, P, Q);

    // Pool + head
    pool_kernel<<<Gg, Hh>>>(batch, Q, b3);
    final_kernel<<<1, 128>>>(Wl, bl, out);
}

// round 13
// speedup vs baseline: 1.7028x; 1.7028x over previous
#include <cuda_runtime.h>

#define Nn 50000
#define Ee 600000
#define Hh 128
#define Gg 64

#define SCAN_T 512
#define SCAN_B ((Nn + SCAN_T - 1) / SCAN_T)   // 98

// ---- static scratch ----
__device__ float g_h[Nn * Hh];
__device__ float g_P[Nn * Hh];      // gemm self-loop-init output
__device__ float g_Q[Nn * Hh];      // aggregated output
__device__ float g_dinv[Nn];
__device__ int   g_deg[Nn];         // edge-in count (no self loop)
__device__ int   g_rank[Ee];        // per-edge slot within its dst row
__device__ int   g_rowptr[Nn + 1];
__device__ int   g_bsum[SCAN_B];
__device__ int2  g_csr[Ee];
__device__ float g_pooled[Gg * Hh];

// ------------------------------------------------------------------
__global__ void init_kernel() {
    int i = blockIdx.x * blockDim.x + threadIdx.x;
    if (i < Nn) g_deg[i] = 0;
    if (i == 0) g_rowptr[Nn] = Ee;
}

// deg count; returned old value is this edge's unique rank in its row
__global__ void deg_kernel(const int* __restrict__ dst) {
    int e = blockIdx.x * blockDim.x + threadIdx.x;
    if (e < Ee) g_rank[e] = atomicAdd(&g_deg[dst[e]], 1);
}

// ---- block sums of deg (CSR counts) + dinv = rsqrt(deg+1) ----
__global__ void scanA_kernel() {
    __shared__ int ws[16];
    int tid = threadIdx.x;
    int i = blockIdx.x * SCAN_T + tid;
    int v = 0;
    if (i < Nn) {
        int d = g_deg[i];
        v = d;
        g_dinv[i] = rsqrtf((float)(d + 1));
    }
#pragma unroll
    for (int o = 16; o; o >>= 1) v += __shfl_down_sync(0xffffffffu, v, o);
    if ((tid & 31) == 0) ws[tid >> 5] = v;
    __syncthreads();
    if (tid < 32) {
        int t = (tid < 16) ? ws[tid] : 0;
#pragma unroll
        for (int o = 8; o; o >>= 1) t += __shfl_down_sync(0xffffffffu, t, o);
        if (tid == 0) g_bsum[blockIdx.x] = t;
    }
}

// ---- full exclusive scan: per-block prefix + fused block-offset reduce ----
__global__ void scanC_kernel() {
    __shared__ int wsum[16], woff[16];
    __shared__ int s_boff;
    int tid = threadIdx.x;
    int lane = tid & 31, wid = tid >> 5;
    int i = blockIdx.x * SCAN_T + tid;
    int v = (i < Nn) ? g_deg[i] : 0;
    int incl = v;
#pragma unroll
    for (int o = 1; o < 32; o <<= 1) {
        int u = __shfl_up_sync(0xffffffffu, incl, o);
        if (lane >= o) incl += u;
    }
    if (lane == 31) wsum[wid] = incl;
    __syncthreads();
    if (tid < 32) {
        int t = (tid < 16) ? wsum[tid] : 0;
        int inc = t;
#pragma unroll
        for (int o = 1; o < 16; o <<= 1) {
            int u = __shfl_up_sync(0xffffffffu, inc, o);
            if (lane >= o) inc += u;
        }
        if (tid < 16) woff[tid] = inc - t;
        int acc = 0;
        for (int t2 = lane; t2 < blockIdx.x; t2 += 32) acc += g_bsum[t2];
#pragma unroll
        for (int o = 16; o; o >>= 1) acc += __shfl_down_sync(0xffffffffu, acc, o);
        if (lane == 0) s_boff = acc;
    }
    __syncthreads();
    if (i < Nn) g_rowptr[i] = incl - v + woff[wid] + s_boff;
}

// atomic-free CSR fill using precomputed ranks
__global__ void fill_kernel(const int* __restrict__ src, const int* __restrict__ dst) {
    int e = blockIdx.x * blockDim.x + threadIdx.x;
    if (e >= Ee) return;
    int s = src[e], d = dst[e];
    int p = g_rowptr[d] + g_rank[e];
    g_csr[p] = make_int2(s, __float_as_int(g_dinv[s] * g_dinv[d]));
}

// ------------------------------------------------------------------
// GEMM: h = f(in) @ W  (f = relu(v+bprev) if apply_f)
// Packed f32x2 FMA. Tile 128x128, 512 threads, 8x4 microtile.
// (R8-proven: 48.2 us, regs=101)
// Epilogue: hout = h, accout = h * dinv^2 (self-loop).
// ------------------------------------------------------------------
__global__ void __launch_bounds__(512, 1)
gemm_kernel(const float* __restrict__ in, const float* __restrict__ W,
            const float* __restrict__ bprev, int apply_f,
            float* __restrict__ hout, float* __restrict__ accout) {
    extern __shared__ float sm[];
    float* in_s = sm;              // [128][128]
    float* W_s  = sm + 128 * 128;  // [128][128]
    int tid = threadIdx.x;
    int r0 = blockIdx.x * 128;

    // load W (128x128): 4096 float4 / 512 threads = 8 each
#pragma unroll
    for (int i = 0; i < 8; i++) {
        int fid = tid + i * 512;
        ((float4*)W_s)[fid] = ((const float4*)W)[fid];
    }
    // load input tile (128x128): 4096 float4 / 512 = 8 each, fused bias+relu
#pragma unroll
    for (int i = 0; i < 8; i++) {
        int fid = tid + i * 512;
        int row = fid >> 5, c4 = fid & 31;
        float4 v = make_float4(0.f, 0.f, 0.f, 0.f);
        if (r0 + row < Nn) {
            v = ((const float4*)(in + (size_t)(r0 + row) * Hh))[c4];
            if (apply_f) {
                float4 b = ((const float4*)bprev)[c4];
                v.x = fmaxf(v.x + b.x, 0.f);
                v.y = fmaxf(v.y + b.y, 0.f);
                v.z = fmaxf(v.z + b.z, 0.f);
                v.w = fmaxf(v.w + b.w, 0.f);
            }
        }
        ((float4*)in_s)[fid] = v;
    }
    __syncthreads();

    int tx = tid & 31;   // col quad: cols tx*4 .. tx*4+3
    int ty = tid >> 5;   // row octet: rows ty*8 .. ty*8+7 (warp-uniform)

    unsigned long long acc[8][2];
#pragma unroll
    for (int r = 0; r < 8; r++) { acc[r][0] = 0ull; acc[r][1] = 0ull; }

#pragma unroll 8
    for (int k = 0; k < Hh; k++) {
        longlong2 bp = ((const longlong2*)(W_s + k * Hh + tx * 4))[0];
        unsigned long long b0 = (unsigned long long)bp.x;
        unsigned long long b1 = (unsigned long long)bp.y;
#pragma unroll
        for (int r = 0; r < 8; r++) {
            float a = in_s[(ty * 8 + r) * Hh + k];
            unsigned long long a2;
            asm("mov.b64 %0, {%1, %1};" : "=l"(a2) : "f"(a));
            asm("fma.rn.f32x2 %0, %1, %2, %0;" : "+l"(acc[r][0]) : "l"(a2), "l"(b0));
            asm("fma.rn.f32x2 %0, %1, %2, %0;" : "+l"(acc[r][1]) : "l"(a2), "l"(b1));
        }
    }

#pragma unroll
    for (int r = 0; r < 8; r++) {
        int row = r0 + ty * 8 + r;
        if (row < Nn) {
            float di = g_dinv[row];
            float d2 = di * di;
            float v[4];
            asm("mov.b64 {%0, %1}, %2;" : "=f"(v[0]), "=f"(v[1]) : "l"(acc[r][0]));
            asm("mov.b64 {%0, %1}, %2;" : "=f"(v[2]), "=f"(v[3]) : "l"(acc[r][1]));
            ((float4*)(hout + (size_t)row * Hh + tx * 4))[0] =
                make_float4(v[0], v[1], v[2], v[3]);
            ((float4*)(accout + (size_t)row * Hh + tx * 4))[0] =
                make_float4(v[0] * d2, v[1] * d2, v[2] * d2, v[3] * d2);
        }
    }
}

// ------------------------------------------------------------------
// Aggregation: warp per node, non-atomic.
// 4 independent accumulator chains -> 4 L2 gathers in flight/warp.
// out[i] = init[i] + sum_{edges j->i} w_j * h[src_j]
// ------------------------------------------------------------------
__global__ void agg_kernel(const float* __restrict__ h, const float* __restrict__ init,
                           float* __restrict__ out) {
    int warp = (blockIdx.x * blockDim.x + threadIdx.x) >> 5;
    int lane = threadIdx.x & 31;
    if (warp >= Nn) return;
    int beg = g_rowptr[warp], end = g_rowptr[warp + 1];
    float4 a0 = ((const float4*)(init + (size_t)warp * Hh))[lane];
    float4 a1 = make_float4(0.f, 0.f, 0.f, 0.f);
    float4 a2 = make_float4(0.f, 0.f, 0.f, 0.f);
    float4 a3 = make_float4(0.f, 0.f, 0.f, 0.f);
    int j = beg;
    for (; j + 4 <= end; j += 4) {
        int2 e0 = g_csr[j];
        int2 e1 = g_csr[j + 1];
        int2 e2 = g_csr[j + 2];
        int2 e3 = g_csr[j + 3];
        float4 v0 = ((const float4*)(h + (size_t)e0.x * Hh))[lane];
        float4 v1 = ((const float4*)(h + (size_t)e1.x * Hh))[lane];
        float4 v2 = ((const float4*)(h + (size_t)e2.x * Hh))[lane];
        float4 v3 = ((const float4*)(h + (size_t)e3.x * Hh))[lane];
        float w0 = __int_as_float(e0.y), w1 = __int_as_float(e1.y);
        float w2 = __int_as_float(e2.y), w3 = __int_as_float(e3.y);
        a0.x = fmaf(w0, v0.x, a0.x); a0.y = fmaf(w0, v0.y, a0.y);
        a0.z = fmaf(w0, v0.z, a0.z); a0.w = fmaf(w0, v0.w, a0.w);
        a1.x = fmaf(w1, v1.x, a1.x); a1.y = fmaf(w1, v1.y, a1.y);
        a1.z = fmaf(w1, v1.z, a1.z); a1.w = fmaf(w1, v1.w, a1.w);
        a2.x = fmaf(w2, v2.x, a2.x); a2.y = fmaf(w2, v2.y, a2.y);
        a2.z = fmaf(w2, v2.z, a2.z); a2.w = fmaf(w2, v2.w, a2.w);
        a3.x = fmaf(w3, v3.x, a3.x); a3.y = fmaf(w3, v3.y, a3.y);
        a3.z = fmaf(w3, v3.z, a3.z); a3.w = fmaf(w3, v3.w, a3.w);
    }
    for (; j < end; j++) {
        int2 e0 = g_csr[j];
        float w0 = __int_as_float(e0.y);
        float4 v0 = ((const float4*)(h + (size_t)e0.x * Hh))[lane];
        a0.x = fmaf(w0, v0.x, a0.x); a0.y = fmaf(w0, v0.y, a0.y);
        a0.z = fmaf(w0, v0.z, a0.z); a0.w = fmaf(w0, v0.w, a0.w);
    }
    a0.x += (a1.x + a2.x) + a3.x;
    a0.y += (a1.y + a2.y) + a3.y;
    a0.z += (a1.z + a2.z) + a3.z;
    a0.w += (a1.w + a2.w) + a3.w;
    ((float4*)(out + (size_t)warp * Hh))[lane] = a0;
}

// ------------------------------------------------------------------
__device__ __forceinline__ int lower_bound_dev(const int* a, int n, int key) {
    int lo = 0, hi = n;
    while (lo < hi) {
        int mid = (lo + hi) >> 1;
        if (a[mid] < key) lo = mid + 1; else hi = mid;
    }
    return lo;
}

__global__ void pool_kernel(const int* __restrict__ batch, const float* __restrict__ acc,
                            const float* __restrict__ b3) {
    int g = blockIdx.x;
    int f = threadIdx.x;
    __shared__ int s_lo, s_hi;
    if (f == 0) s_lo = lower_bound_dev(batch, Nn, g);
    if (f == 1) s_hi = lower_bound_dev(batch, Nn, g + 1);
    __syncthreads();
    int lo = s_lo, hi = s_hi;
    float b = b3[f];
    float s0 = 0.f, s1 = 0.f, s2 = 0.f, s3 = 0.f;
    int n = lo;
    for (; n + 4 <= hi; n += 4) {
        s0 += fmaxf(acc[(size_t)(n + 0) * Hh + f] + b, 0.f);
        s1 += fmaxf(acc[(size_t)(n + 1) * Hh + f] + b, 0.f);
        s2 += fmaxf(acc[(size_t)(n + 2) * Hh + f] + b, 0.f);
        s3 += fmaxf(acc[(size_t)(n + 3) * Hh + f] + b, 0.f);
    }
    for (; n < hi; n++) s0 += fmaxf(acc[(size_t)n * Hh + f] + b, 0.f);
    float s = (s0 + s1) + (s2 + s3);
    g_pooled[g * Hh + f] = s / fmaxf((float)(hi - lo), 1.f);
}

__global__ void final_kernel(const float* __restrict__ Wl, const float* __restrict__ bl,
                             float* __restrict__ out) {
    int t = threadIdx.x;
    int g = t >> 1, c = t & 1;
    float s = 0.f;
#pragma unroll 8
    for (int k = 0; k < Hh; k++)
        s += g_pooled[g * Hh + k] * Wl[k * 2 + c];
    out[g * 2 + c] = s + bl[c];
}

// ------------------------------------------------------------------
extern "C" void kernel_launch(void* const* d_in, const int* in_sizes, int n_in,
                              void* d_out, int out_size) {
    const float* x     = (const float*)d_in[0];
    const int*   ei    = (const int*)d_in[1];
    const int*   batch = (const int*)d_in[2];
    const float* W1 = (const float*)d_in[3];
    const float* b1 = (const float*)d_in[4];
    const float* W2 = (const float*)d_in[5];
    const float* b2 = (const float*)d_in[6];
    const float* W3 = (const float*)d_in[7];
    const float* b3 = (const float*)d_in[8];
    const float* Wl = (const float*)d_in[9];
    const float* bl = (const float*)d_in[10];
    float* out = (float*)d_out;

    const int* src = ei;
    const int* dst = ei + Ee;

    float *hptr, *P, *Q;
    cudaGetSymbolAddress((void**)&hptr, g_h);
    cudaGetSymbolAddress((void**)&P, g_P);
    cudaGetSymbolAddress((void**)&Q, g_Q);

    const int SMEM = 2 * Hh * Hh * sizeof(float);   // 128 KB
    cudaFuncSetAttribute(gemm_kernel, cudaFuncAttributeMaxDynamicSharedMemorySize, SMEM);

    int gemm_blocks = (Nn + 127) / 128;              // 391
    int agg_blocks  = (Nn * 32 + 255) / 256;

    // #1..#3: minimal prefix so gemm1 is launch #4 (ncu captures #4)
    init_kernel<<<(Nn + 255) / 256, 256>>>();
    deg_kernel<<<(Ee + 255) / 256, 256>>>(dst);      // also writes ranks
    scanA_kernel<<<SCAN_B, SCAN_T>>>();              // block sums + dinv

    // #4: layer-1 GEMM (needs only dinv)
    gemm_kernel<<<gemm_blocks, 512, SMEM>>>(x, W1, nullptr, 0, hptr, P);

    // finish CSR build, then aggregate
    scanC_kernel<<<SCAN_B, SCAN_T>>>();
    fill_kernel<<<(Ee + 255) / 256, 256>>>(src, dst);
    agg_kernel<<<agg_blocks, 256>>>(hptr, P, Q);

    // Layer 2
    gemm_kernel<<<gemm_blocks, 512, SMEM>>>(Q, W2, b1, 1, hptr, P);
    agg_kernel<<<agg_blocks, 256>>>(hptr, P, Q);
    // Layer 3
    gemm_kernel<<<gemm_blocks, 512, SMEM>>>(Q, W3, b2, 1, hptr, P);
    agg_kernel<<<agg_blocks, 256>>>(hptr, P, Q);

    // Pool + head
    pool_kernel<<<Gg, Hh>>>(batch, Q, b3);
    final_kernel<<<1, 128>>>(Wl, bl, out);
}